// round 1
// baseline (speedup 1.0000x reference)
#include <cuda_runtime.h>
#include <cstdint>

#define BATCH 8
#define NPIX (1 << 20)
#define HARD_IND 524288u
#define PSOFT (104857.0 / 1048576.0)
#define TOTAL_ELEMS 25165824.0

// ---------------- scratch (static device memory; no allocations) ----------------
__device__ float    g_res[BATCH * NPIX];          // 32 MB: per-pixel channel-summed |x-y|
__device__ unsigned g_hist1[BATCH][4096];         // level-1 histogram (float bits >> 20)
__device__ unsigned g_hist2[BATCH][1 << 20];      // 32 MB: low-20-bit histogram inside candidate bin
__device__ double   g_sumAll[BATCH];
__device__ double   g_hardHigh[BATCH];            // sum of res in bins strictly above candidate bin
__device__ int      g_cand[BATCH];
__device__ unsigned g_above[BATCH];               // count strictly above candidate bin
__device__ unsigned g_chunkCnt[BATCH][1024];
__device__ double   g_chunkVal[BATCH][1024];
__device__ double   g_total;

// ---------------- K0: zero scratch ----------------
__global__ void k_zero() {
    unsigned idx = blockIdx.x * blockDim.x + threadIdx.x;
    unsigned stride = gridDim.x * blockDim.x;
    uint4 z = make_uint4(0, 0, 0, 0);
    uint4* p2 = reinterpret_cast<uint4*>(&g_hist2[0][0]);
    const unsigned n2 = (BATCH * (1u << 20)) / 4;
    for (unsigned i = idx; i < n2; i += stride) p2[i] = z;
    uint4* p1 = reinterpret_cast<uint4*>(&g_hist1[0][0]);
    const unsigned n1 = (BATCH * 4096) / 4;
    if (idx < n1) p1[idx] = z;
    if (idx < BATCH) { g_sumAll[idx] = 0.0; g_hardHigh[idx] = 0.0; }
    if (idx == 0) g_total = 0.0;
}

// ---------------- K1: res = sum_c |x-y|, level-1 histogram, total sum ----------------
__global__ void __launch_bounds__(256) k_res(const float* __restrict__ x,
                                             const float* __restrict__ y) {
    __shared__ unsigned sh[4096];
    for (int i = threadIdx.x; i < 4096; i += 256) sh[i] = 0;
    __syncthreads();

    const int blocksPerBatch = NPIX / 4096;   // 256
    int b   = blockIdx.x / blocksPerBatch;
    int blk = blockIdx.x % blocksPerBatch;
    const float* xb = x + (size_t)b * 3 * NPIX;
    const float* yb = y + (size_t)b * 3 * NPIX;
    float* rb = g_res + (size_t)b * NPIX;
    int pix0 = blk * 4096;
    double lsum = 0.0;

#pragma unroll
    for (int it = 0; it < 4; ++it) {
        int i = pix0 + it * 1024 + threadIdx.x * 4;
        float4 a0 = *(const float4*)(xb + i);
        float4 b0 = *(const float4*)(yb + i);
        float4 a1 = *(const float4*)(xb + NPIX + i);
        float4 b1 = *(const float4*)(yb + NPIX + i);
        float4 a2 = *(const float4*)(xb + 2 * NPIX + i);
        float4 b2 = *(const float4*)(yb + 2 * NPIX + i);
        float4 r;
        r.x = (fabsf(a0.x - b0.x) + fabsf(a1.x - b1.x)) + fabsf(a2.x - b2.x);
        r.y = (fabsf(a0.y - b0.y) + fabsf(a1.y - b1.y)) + fabsf(a2.y - b2.y);
        r.z = (fabsf(a0.z - b0.z) + fabsf(a1.z - b1.z)) + fabsf(a2.z - b2.z);
        r.w = (fabsf(a0.w - b0.w) + fabsf(a1.w - b1.w)) + fabsf(a2.w - b2.w);
        *(float4*)(rb + i) = r;
        atomicAdd(&sh[__float_as_uint(r.x) >> 20], 1u);
        atomicAdd(&sh[__float_as_uint(r.y) >> 20], 1u);
        atomicAdd(&sh[__float_as_uint(r.z) >> 20], 1u);
        atomicAdd(&sh[__float_as_uint(r.w) >> 20], 1u);
        lsum += ((double)r.x + (double)r.y) + ((double)r.z + (double)r.w);
    }

    // block-reduce lsum
    for (int o = 16; o; o >>= 1) lsum += __shfl_down_sync(0xffffffffu, lsum, o);
    __shared__ double wsum[8];
    int lane = threadIdx.x & 31, w = threadIdx.x >> 5;
    if (!lane) wsum[w] = lsum;
    __syncthreads();
    if (threadIdx.x == 0) {
        double s = 0.0;
        for (int i = 0; i < 8; ++i) s += wsum[i];
        atomicAdd(&g_sumAll[b], s);
    }
    // flush privatized histogram
    for (int i = threadIdx.x; i < 4096; i += 256) {
        unsigned c = sh[i];
        if (c) atomicAdd(&g_hist1[b][i], c);
    }
}

// ---------------- K2: find candidate level-1 bin (rank HARD_IND, descending) ------
__global__ void __launch_bounds__(1024) k_sel1() {
    int b = blockIdx.x, tid = threadIdx.x, lane = tid & 31, w = tid >> 5;
    __shared__ unsigned sh[4096];
    for (int i = tid; i < 4096; i += 1024) sh[i] = g_hist1[b][i];
    __syncthreads();
    unsigned v = sh[4 * tid] + sh[4 * tid + 1] + sh[4 * tid + 2] + sh[4 * tid + 3];
    // inclusive suffix scan within warp (toward higher lanes = higher bins)
    unsigned s = v;
    for (int o = 1; o < 32; o <<= 1) {
        unsigned t = __shfl_down_sync(0xffffffffu, s, o);
        if (lane + o < 32) s += t;
    }
    __shared__ unsigned wtot[32];
    if (!lane) wtot[w] = s;
    __syncthreads();
    unsigned above = 0;
    for (int u = w + 1; u < 32; ++u) above += wtot[u];
    unsigned suffExcl = above + s - v;   // count in groups strictly above this group
    if (suffExcl <= HARD_IND && HARD_IND < suffExcl + v) {
        unsigned cum = suffExcl;
        for (int j = 3; j >= 0; --j) {   // descending bins within group
            unsigned c = sh[4 * tid + j];
            if (cum + c > HARD_IND) { g_cand[b] = 4 * tid + j; g_above[b] = cum; break; }
            cum += c;
        }
    }
}

// ---------------- K3: hard-high sum + low-20-bit histogram of candidate bin -------
__global__ void __launch_bounds__(256) k_refine() {
    const int blocksPerBatch = NPIX / 4096;
    int b   = blockIdx.x / blocksPerBatch;
    int blk = blockIdx.x % blocksPerBatch;
    int cand = g_cand[b];
    const float* rb = g_res + (size_t)b * NPIX;
    unsigned* h2 = &g_hist2[b][0];
    int pix0 = blk * 4096;
    double lhigh = 0.0;

#pragma unroll
    for (int it = 0; it < 4; ++it) {
        int i = pix0 + it * 1024 + threadIdx.x * 4;
        float4 r = *(const float4*)(rb + i);
        float vv[4] = {r.x, r.y, r.z, r.w};
#pragma unroll
        for (int k = 0; k < 4; ++k) {
            unsigned bits = __float_as_uint(vv[k]);
            int bin = (int)(bits >> 20);
            if (bin > cand)       lhigh += (double)vv[k];
            else if (bin == cand) atomicAdd(&h2[bits & 0xFFFFFu], 1u);
        }
    }
    for (int o = 16; o; o >>= 1) lhigh += __shfl_down_sync(0xffffffffu, lhigh, o);
    __shared__ double wsum[8];
    int lane = threadIdx.x & 31, w = threadIdx.x >> 5;
    if (!lane) wsum[w] = lhigh;
    __syncthreads();
    if (!threadIdx.x) {
        double s = 0.0;
        for (int i = 0; i < 8; ++i) s += wsum[i];
        atomicAdd(&g_hardHigh[b], s);
    }
}

// ---------------- K4a: chunk summaries of hist2 (warp per 1024-bin chunk) ---------
__global__ void __launch_bounds__(256) k_chunks() {
    int gw = (blockIdx.x * 256 + threadIdx.x) >> 5;   // global warp id, 8192 total
    int lane = threadIdx.x & 31;
    int b = gw >> 10, chunk = gw & 1023;
    unsigned base_bits = ((unsigned)g_cand[b] << 20) | ((unsigned)chunk << 10);
    const unsigned* h2 = &g_hist2[b][(size_t)chunk << 10];
    unsigned cnt = 0; double val = 0.0;
    for (int j = lane; j < 1024; j += 32) {
        unsigned c = h2[j];
        if (c) { cnt += c; val += (double)c * (double)__uint_as_float(base_bits | (unsigned)j); }
    }
    for (int o = 16; o; o >>= 1) {
        cnt += __shfl_down_sync(0xffffffffu, cnt, o);
        val += __shfl_down_sync(0xffffffffu, val, o);
    }
    if (!lane) { g_chunkCnt[b][chunk] = cnt; g_chunkVal[b][chunk] = val; }
}

// ---------------- K4b: exact threshold + per-batch result ----------------
__global__ void __launch_bounds__(1024) k_final() {
    int b = blockIdx.x, tid = threadIdx.x, lane = tid & 31, w = tid >> 5;
    __shared__ unsigned scnt[1024];
    __shared__ double   sval[1024];
    scnt[tid] = g_chunkCnt[b][tid];
    sval[tid] = g_chunkVal[b][tid];
    __syncthreads();

    unsigned v = scnt[tid], s = v;
    for (int o = 1; o < 32; o <<= 1) {
        unsigned t = __shfl_down_sync(0xffffffffu, s, o);
        if (lane + o < 32) s += t;
    }
    __shared__ unsigned wtot[32];
    if (!lane) wtot[w] = s;
    __syncthreads();
    unsigned above = 0;
    for (int u = w + 1; u < 32; ++u) above += wtot[u];
    unsigned suffExcl = above + s - v;

    unsigned r = HARD_IND - g_above[b];   // rank within candidate level-1 bin (descending)
    __shared__ int sT; __shared__ unsigned sRin; __shared__ double sVA;
    if (suffExcl <= r && r < suffExcl + v) {
        double va = 0.0;
        for (int u = tid + 1; u < 1024; ++u) va += sval[u];
        sT = tid; sRin = r - suffExcl; sVA = va;
    }
    __syncthreads();

    int T = sT;
    __shared__ unsigned bins[1024];
    bins[tid] = g_hist2[b][((size_t)T << 10) + tid];
    __syncthreads();

    v = bins[tid]; s = v;
    for (int o = 1; o < 32; o <<= 1) {
        unsigned t = __shfl_down_sync(0xffffffffu, s, o);
        if (lane + o < 32) s += t;
    }
    if (!lane) wtot[w] = s;
    __syncthreads();
    above = 0;
    for (int u = w + 1; u < 32; ++u) above += wtot[u];
    suffExcl = above + s - v;

    unsigned rin = sRin;
    if (suffExcl <= rin && rin < suffExcl + v) {
        unsigned baseb = ((unsigned)g_cand[b] << 20) | ((unsigned)T << 10);
        double pv = 0.0;
        for (int u = tid + 1; u < 1024; ++u)
            if (bins[u]) pv += (double)bins[u] * (double)__uint_as_float(baseb | (unsigned)u);
        double hardSum = g_hardHigh[b] + sVA + pv;           // exact sum of res > thre
        double result  = hardSum + PSOFT * (g_sumAll[b] - hardSum);
        atomicAdd(&g_total, result);
    }
}

// ---------------- K5: final scalar ----------------
__global__ void k_out(float* out) {
    out[0] = (float)(g_total / TOTAL_ELEMS);
}

extern "C" void kernel_launch(void* const* d_in, const int* in_sizes, int n_in,
                              void* d_out, int out_size) {
    const float* x = (const float*)d_in[0];
    const float* y = (const float*)d_in[1];
    float* out = (float*)d_out;
    k_zero  <<<2048, 256>>>();
    k_res   <<<2048, 256>>>(x, y);
    k_sel1  <<<BATCH, 1024>>>();
    k_refine<<<2048, 256>>>();
    k_chunks<<<1024, 256>>>();
    k_final <<<BATCH, 1024>>>();
    k_out   <<<1, 1>>>(out);
}